// round 16
// baseline (speedup 1.0000x reference)
#include <cuda_runtime.h>
#include <math.h>

#define BB 128
#define CC 62
#define LL 2000
#define NW 36
#define DMM 128
#define NCL 5

__device__ float g_feats[BB*CC*504];
__device__ float g_pf[BB*CC*DMM];
__device__ float g_projWT[504*DMM];
__device__ float g_WqkvT[3*DMM*384];
__device__ float g_WoT[3*DMM*DMM];
__device__ float g_W1T[3*DMM*256];
__device__ float g_W2T[3*256*DMM];
__device__ float g_B50[52*96];
__device__ int   g_tempassign[BB*CC];
__device__ int   g_assign[CC];

__global__ void k_init(const float* __restrict__ proj_w, const float* __restrict__ Wqkv,
                       const float* __restrict__ Wo, const float* __restrict__ W1,
                       const float* __restrict__ W2){
  int stride = gridDim.x*blockDim.x;
  int t0 = blockIdx.x*blockDim.x + threadIdx.x;
  for (int t=t0; t<52*96; t+=stride){
    int m=t/96, c=t%96, f=c>>1;
    float v=0.0f;
    if(m<50 && c<92){
      double ang = 6.283185307179586476925286766559 * (double)(f*m) / 250.0;
      v = (c&1)? (float)(-sin(ang)) : (float)cos(ang);
    }
    g_B50[t]=v;
  }
  for (int t=t0; t<504*DMM; t+=stride){ int k=t/DMM, j=t%DMM; g_projWT[t]=proj_w[j*504+k]; }
  for (int t=t0; t<3*DMM*384; t+=stride){ int l=t/(DMM*384); int r=t%(DMM*384); int k=r/384, j=r%384;
    g_WqkvT[t]=Wqkv[((size_t)l*384+j)*DMM+k]; }
  for (int t=t0; t<3*DMM*DMM; t+=stride){ int l=t/(DMM*DMM); int r=t%(DMM*DMM); int k=r/DMM, j=r%DMM;
    g_WoT[t]=Wo[((size_t)l*DMM+j)*DMM+k]; }
  for (int t=t0; t<3*DMM*256; t+=stride){ int l=t/(DMM*256); int r=t%(DMM*256); int k=r/256, j=r%256;
    g_W1T[t]=W1[((size_t)l*256+j)*DMM+k]; }
  for (int t=t0; t<3*256*DMM; t+=stride){ int l=t/(256*DMM); int r=t%(256*DMM); int k=r/DMM, j=r%DMM;
    g_W2T[t]=W2[((size_t)l*DMM+j)*256+k]; }
}

__device__ __forceinline__ int argmax62(const float* vals, float* redv, int* redi){
  int tid=threadIdx.x;
  __syncthreads();
  float v=(tid<62)?vals[tid]:-3.4e38f;
  int idx=tid;
  #pragma unroll
  for(int o=16;o;o>>=1){
    float ov=__shfl_xor_sync(0xffffffffu,v,o);
    int oi=__shfl_xor_sync(0xffffffffu,idx,o);
    if(ov>v || (ov==v && oi<idx)){ v=ov; idx=oi; }
  }
  if((tid&31)==0){ redv[tid>>5]=v; redi[tid>>5]=idx; }
  __syncthreads();
  float bv=redv[0]; int bi=redi[0];
  if(redv[1]>bv || (redv[1]==bv && redi[1]<bi)){ bv=redv[1]; bi=redi[1]; }
  return bi;
}

// ---- features: segment DFT (4x4 tile, spill-free @48 regs, 5 blocks/SM) ----
__global__ __launch_bounds__(256,5) void k_feat(const float* __restrict__ x){
  __shared__ float sA[40*52];
  __shared__ float sB[52*96];
  __shared__ float sP[40*96];
  __shared__ float wtab25[50];
  int bc = blockIdx.x, tid = threadIdx.x;
  const float* xr = x + (size_t)bc*LL;
  for (int i=tid;i<40*52;i+=256){ int s=i/52,m=i%52; sA[i]=(m<50)? xr[s*50+m] : 0.0f; }
  for (int i=tid;i<52*96;i+=256) sB[i]=g_B50[i];
  if (tid<25){
    int fm=tid/5, j=tid%5;
    int m5=(fm*j)%5;
    float ang = 6.2831853071795864769f * (float)m5 / 5.0f;
    wtab25[tid*2]=cosf(ang); wtab25[tid*2+1]=-sinf(ang);
  }
  __syncthreads();
  if (tid<240){
    int sg=tid/24, cg=tid%24;
    float acc[4][4];
    #pragma unroll
    for(int r=0;r<4;r++){ acc[r][0]=0;acc[r][1]=0;acc[r][2]=0;acc[r][3]=0; }
    const float* A0=&sA[(sg*4+0)*52];
    const float* A1=&sA[(sg*4+1)*52];
    const float* A2=&sA[(sg*4+2)*52];
    const float* A3=&sA[(sg*4+3)*52];
    #pragma unroll 1
    for(int k=0;k<52;k+=4){
      float4 a0=*(const float4*)&A0[k];
      float4 a1=*(const float4*)&A1[k];
      float4 a2=*(const float4*)&A2[k];
      float4 a3=*(const float4*)&A3[k];
      #pragma unroll
      for(int kk=0;kk<4;kk++){
        float4 bv=*(const float4*)&sB[(k+kk)*96+cg*4];
        float e0=kk==0?a0.x:kk==1?a0.y:kk==2?a0.z:a0.w;
        float e1=kk==0?a1.x:kk==1?a1.y:kk==2?a1.z:a1.w;
        float e2=kk==0?a2.x:kk==1?a2.y:kk==2?a2.z:a2.w;
        float e3=kk==0?a3.x:kk==1?a3.y:kk==2?a3.z:a3.w;
        acc[0][0]=fmaf(e0,bv.x,acc[0][0]); acc[0][1]=fmaf(e0,bv.y,acc[0][1]);
        acc[0][2]=fmaf(e0,bv.z,acc[0][2]); acc[0][3]=fmaf(e0,bv.w,acc[0][3]);
        acc[1][0]=fmaf(e1,bv.x,acc[1][0]); acc[1][1]=fmaf(e1,bv.y,acc[1][1]);
        acc[1][2]=fmaf(e1,bv.z,acc[1][2]); acc[1][3]=fmaf(e1,bv.w,acc[1][3]);
        acc[2][0]=fmaf(e2,bv.x,acc[2][0]); acc[2][1]=fmaf(e2,bv.y,acc[2][1]);
        acc[2][2]=fmaf(e2,bv.z,acc[2][2]); acc[2][3]=fmaf(e2,bv.w,acc[2][3]);
        acc[3][0]=fmaf(e3,bv.x,acc[3][0]); acc[3][1]=fmaf(e3,bv.y,acc[3][1]);
        acc[3][2]=fmaf(e3,bv.z,acc[3][2]); acc[3][3]=fmaf(e3,bv.w,acc[3][3]);
      }
    }
    #pragma unroll
    for(int r=0;r<4;r++)
      *(float4*)&sP[(sg*4+r)*96 + cg*4] = make_float4(acc[r][0],acc[r][1],acc[r][2],acc[r][3]);
  }
  __syncthreads();
  float* Y = sB;
  for(int t=tid;t<NW*46;t+=256){
    int w=t/46, f=t%46, fm=f%5;
    const float* wt=&wtab25[fm*10];
    float yre=0, yim=0;
    #pragma unroll
    for(int j=0;j<5;j++){
      float wr=wt[j*2], wi=wt[j*2+1];
      float pr=sP[(w+j)*96+2*f], pi=sP[(w+j)*96+2*f+1];
      yre=fmaf(wr,pr,yre); yre=fmaf(-wi,pi,yre);
      yim=fmaf(wr,pi,yim); yim=fmaf(wi,pr,yim);
    }
    Y[w*92+2*f]=yre; Y[w*92+2*f+1]=yim;
  }
  __syncthreads();
  float* ps = sA;
  for(int t=tid;t<NW*44;t+=256){
    int w=t/44, fi=t%44, f=fi+1;
    float xre=0.5f*Y[w*92+2*f]   - 0.25f*(Y[w*92+2*(f-1)]   + Y[w*92+2*(f+1)]);
    float xim=0.5f*Y[w*92+2*f+1] - 0.25f*(Y[w*92+2*(f-1)+1] + Y[w*92+2*(f+1)+1]);
    ps[w*44+fi]=(xre*xre+xim*xim)*(1.0f/250.0f);
  }
  __syncthreads();
  const int blo[7]={1,4,8,12,16,20,30};
  const int bhi[7]={4,8,12,16,20,30,45};
  float vp=0.0f, vd=0.0f;
  if (tid<252){
    int w=tid/7,bd=tid%7;
    float s=0;
    for(int f=blo[bd];f<bhi[bd];f++) s+=ps[w*44+f-1];
    vp=s/(float)(bhi[bd]-blo[bd]);
    vd=0.5f*logf(17.079468445347132f*vp+1e-9f);
  }
  float4 r; r.x=vp; r.y=vp*vp; r.z=vd; r.w=vd*vd;
  #pragma unroll
  for(int o=16;o;o>>=1){
    r.x+=__shfl_xor_sync(0xffffffffu,r.x,o);
    r.y+=__shfl_xor_sync(0xffffffffu,r.y,o);
    r.z+=__shfl_xor_sync(0xffffffffu,r.z,o);
    r.w+=__shfl_xor_sync(0xffffffffu,r.w,o);
  }
  float4* red4=(float4*)sP;
  if((tid&31)==0) red4[tid>>5]=r;
  __syncthreads();
  float4 t4=red4[0];
  #pragma unroll
  for(int w=1;w<8;w++){ float4 q=red4[w]; t4.x+=q.x; t4.y+=q.y; t4.z+=q.z; t4.w+=q.w; }
  float mp=t4.x*(1.0f/252.0f);
  float sdp=sqrtf(fmaxf(t4.y-252.0f*mp*mp,0.0f)*(1.0f/251.0f));
  float md_=t4.z*(1.0f/252.0f);
  float sdd=sqrtf(fmaxf(t4.w-252.0f*md_*md_,0.0f)*(1.0f/251.0f));
  if(tid<252){
    int w=tid/7,bd=tid%7;
    size_t base=(size_t)bc*504;
    g_feats[base + w*14 + bd]     =(vp-mp)/(sdp+1e-9f);
    g_feats[base + w*14 + 7 + bd] =(vd-md_)/(sdd+1e-9f);
  }
}

// ---- FUSED: k_proj 32-row tiles (blocks 128..375) + k_fps (blocks 0..127) ----
union SmemU {
  struct { float sAT[56*36]; float sW[56*128]; } proj;
  struct { float G[62*62]; float tileT[84*68]; float rsum[62]; float md[62]; float nrm[62];
           float redv[8]; float cc[NCL*3]; float ncc[NCL]; int redi[8]; int idx5[NCL]; } fps;
};

__global__ __launch_bounds__(256) void k_projfps(const float* __restrict__ proj_b,
    const float* __restrict__ lng, const float* __restrict__ lnb,
    const float* __restrict__ pos_emb){
  __shared__ SmemU u;
  int tid=threadIdx.x;
  if(blockIdx.x>=128){
    float* sAT=u.proj.sAT;
    float* sW=u.proj.sW;
    int tr=tid>>5, tc=tid&31;
    int row0=(blockIdx.x-128)*32;
    float acc[4][4];
    {
      float4 pb=*(const float4*)&proj_b[4*tc];
      #pragma unroll
      for(int r=0;r<4;r++){ acc[r][0]=pb.x; acc[r][1]=pb.y; acc[r][2]=pb.z; acc[r][3]=pb.w; }
    }
    for(int kc=0;kc<504;kc+=56){
      #pragma unroll 4
      for(int i=tid;i<56*32;i+=256){ int k=i%56, r=i/56;
        sAT[k*36+r]=g_feats[(size_t)(row0+r)*504+kc+k]; }
      #pragma unroll 4
      for(int i=tid;i<56*128;i+=256) sW[i]=g_projWT[(size_t)(kc+(i>>7))*128+(i&127)];
      __syncthreads();
      #pragma unroll 4
      for(int k=0;k<56;k++){
        float4 a0=*(const float4*)&sAT[k*36+4*tr];
        float4 w =*(const float4*)&sW[k*128+4*tc];
        acc[0][0]=fmaf(a0.x,w.x,acc[0][0]); acc[0][1]=fmaf(a0.x,w.y,acc[0][1]); acc[0][2]=fmaf(a0.x,w.z,acc[0][2]); acc[0][3]=fmaf(a0.x,w.w,acc[0][3]);
        acc[1][0]=fmaf(a0.y,w.x,acc[1][0]); acc[1][1]=fmaf(a0.y,w.y,acc[1][1]); acc[1][2]=fmaf(a0.y,w.z,acc[1][2]); acc[1][3]=fmaf(a0.y,w.w,acc[1][3]);
        acc[2][0]=fmaf(a0.z,w.x,acc[2][0]); acc[2][1]=fmaf(a0.z,w.y,acc[2][1]); acc[2][2]=fmaf(a0.z,w.z,acc[2][2]); acc[2][3]=fmaf(a0.z,w.w,acc[2][3]);
        acc[3][0]=fmaf(a0.w,w.x,acc[3][0]); acc[3][1]=fmaf(a0.w,w.y,acc[3][1]); acc[3][2]=fmaf(a0.w,w.z,acc[3][2]); acc[3][3]=fmaf(a0.w,w.w,acc[3][3]);
      }
      __syncthreads();
    }
    float4 g=*(const float4*)&lng[4*tc];
    float4 bb=*(const float4*)&lnb[4*tc];
    #pragma unroll
    for(int r=0;r<4;r++){
      float s=acc[r][0]+acc[r][1]+acc[r][2]+acc[r][3];
      #pragma unroll
      for(int o=16;o;o>>=1) s+=__shfl_xor_sync(0xffffffffu,s,o);
      float m=s*(1.0f/128.0f);
      float d0=acc[r][0]-m,d1=acc[r][1]-m,d2=acc[r][2]-m,d3=acc[r][3]-m;
      float q=d0*d0+d1*d1+d2*d2+d3*d3;
      #pragma unroll
      for(int o=16;o;o>>=1) q+=__shfl_xor_sync(0xffffffffu,q,o);
      float rstd=rsqrtf(q*(1.0f/128.0f)+1e-5f);
      float4 o4;
      o4.x=fmaxf(fmaf(d0*rstd,g.x,bb.x),0.0f);
      o4.y=fmaxf(fmaf(d1*rstd,g.y,bb.y),0.0f);
      o4.z=fmaxf(fmaf(d2*rstd,g.z,bb.z),0.0f);
      o4.w=fmaxf(fmaf(d3*rstd,g.w,bb.w),0.0f);
      *(float4*)&g_pf[(size_t)(row0+4*tr+r)*128+4*tc]=o4;
    }
  } else {
    float* G=u.fps.G;
    float* tileT=u.fps.tileT;
    float* rsum=u.fps.rsum;
    float* md=u.fps.md;
    float* nrm=u.fps.nrm;
    float* redv=u.fps.redv;
    int*   redi=u.fps.redi;
    int*   idx5=u.fps.idx5;
    float* cc=u.fps.cc;
    float* ncc=u.fps.ncc;
    int b=blockIdx.x;
    int tr=tid>>4, tc=tid&15;
    float acc[4][4];
    #pragma unroll
    for(int r=0;r<4;r++){ acc[r][0]=0;acc[r][1]=0;acc[r][2]=0;acc[r][3]=0; }
    for(int c0=0;c0<504;c0+=84){
      #pragma unroll 4
      for(int i=tid;i<84*64;i+=256){ int r=i/84, k=i%84;
        tileT[k*68+r]=(r<62)? g_feats[((size_t)b*62+r)*504+c0+k] : 0.0f; }
      __syncthreads();
      #pragma unroll 4
      for(int k=0;k<84;k++){
        float4 av=*(const float4*)&tileT[k*68+4*tr];
        float4 bv=*(const float4*)&tileT[k*68+4*tc];
        acc[0][0]=fmaf(av.x,bv.x,acc[0][0]); acc[0][1]=fmaf(av.x,bv.y,acc[0][1]); acc[0][2]=fmaf(av.x,bv.z,acc[0][2]); acc[0][3]=fmaf(av.x,bv.w,acc[0][3]);
        acc[1][0]=fmaf(av.y,bv.x,acc[1][0]); acc[1][1]=fmaf(av.y,bv.y,acc[1][1]); acc[1][2]=fmaf(av.y,bv.z,acc[1][2]); acc[1][3]=fmaf(av.y,bv.w,acc[1][3]);
        acc[2][0]=fmaf(av.z,bv.x,acc[2][0]); acc[2][1]=fmaf(av.z,bv.y,acc[2][1]); acc[2][2]=fmaf(av.z,bv.z,acc[2][2]); acc[2][3]=fmaf(av.z,bv.w,acc[2][3]);
        acc[3][0]=fmaf(av.w,bv.x,acc[3][0]); acc[3][1]=fmaf(av.w,bv.y,acc[3][1]); acc[3][2]=fmaf(av.w,bv.z,acc[3][2]); acc[3][3]=fmaf(av.w,bv.w,acc[3][3]);
      }
      __syncthreads();
    }
    #pragma unroll
    for(int r=0;r<4;r++){
      int gr=4*tr+r;
      if(gr<62){
        #pragma unroll
        for(int c=0;c<4;c++){
          int gc=4*tc+c;
          if(gc<62) G[gr*62+gc]=acc[r][c];
        }
      }
    }
    __syncthreads();
    if(tid<62) nrm[tid]=G[tid*62+tid];
    __syncthreads();
    for(int p=tid;p<3844;p+=256){ int i=p/62,j=p%62; G[p]=fmaxf(nrm[i]+nrm[j]-2.0f*G[p],0.0f); }
    __syncthreads();
    {
      int w=tid>>5, lane=tid&31;
      for(int rr=w;rr<62;rr+=8){
        float s=sqrtf(G[rr*62+lane]);
        if(lane+32<62) s+=sqrtf(G[rr*62+lane+32]);
        #pragma unroll
        for(int o=16;o;o>>=1) s+=__shfl_xor_sync(0xffffffffu,s,o);
        if(lane==0) rsum[rr]=s;
      }
    }
    int start=argmax62(rsum,redv,redi);
    if(tid<62) md[tid]=G[start*62+tid];
    if(tid==0) idx5[0]=start;
    for(int it=1;it<NCL;it++){
      int far=argmax62(md,redv,redi);
      if(tid<62) md[tid]=fminf(md[tid],G[far*62+tid]);
      if(tid==0) idx5[it]=far;
    }
    __syncthreads();
    if(tid<NCL*3){ int k=tid/3,d=tid%3; cc[tid]=pos_emb[((size_t)b*62+idx5[k])*3+d]; }
    __syncthreads();
    if(tid<NCL){ float s=0; for(int d=0;d<3;d++) s+=cc[tid*3+d]*cc[tid*3+d]; ncc[tid]=s; }
    __syncthreads();
    if(tid<62){
      float p0=pos_emb[((size_t)b*62+tid)*3+0];
      float p1=pos_emb[((size_t)b*62+tid)*3+1];
      float p2=pos_emb[((size_t)b*62+tid)*3+2];
      float np=p0*p0+p1*p1+p2*p2;
      float best=3.4e38f; int bi=0;
      for(int k=0;k<NCL;k++){
        float dot=p0*cc[k*3]+p1*cc[k*3+1]+p2*cc[k*3+2];
        float d2=fmaxf(np+ncc[k]-2.0f*dot,0.0f);
        if(d2<best){best=d2;bi=k;}
      }
      g_tempassign[b*62+tid]=bi;
    }
  }
}

// ---- global clustering + greedy capacity assignment ----
__global__ __launch_bounds__(256) void k_cluster(const float* __restrict__ pos_emb){
  __shared__ float pos[62*3];
  __shared__ float D[62*62];
  __shared__ float nrm[62];
  __shared__ float rsum[62];
  __shared__ float md[62];
  __shared__ float redv[8];
  __shared__ int   redi[8];
  __shared__ int   idx5[NCL];
  __shared__ float cen[NCL*3];
  __shared__ float redp[256*20];
  __shared__ float avg[NCL*3];
  __shared__ int   order[62*NCL];
  int tid=threadIdx.x;
  if(tid<186) pos[tid]=pos_emb[tid];
  __syncthreads();
  if(tid<62){ float s=0; for(int d=0;d<3;d++) s+=pos[tid*3+d]*pos[tid*3+d]; nrm[tid]=s; }
  __syncthreads();
  for(int p=tid;p<3844;p+=256){ int i=p/62,j=p%62;
    float dot=pos[i*3]*pos[j*3]+pos[i*3+1]*pos[j*3+1]+pos[i*3+2]*pos[j*3+2];
    D[p]=fmaxf(nrm[i]+nrm[j]-2.0f*dot,0.0f); }
  __syncthreads();
  {
    int w=tid>>5, lane=tid&31;
    for(int rr=w;rr<62;rr+=8){
      float s=sqrtf(D[rr*62+lane]);
      if(lane+32<62) s+=sqrtf(D[rr*62+lane+32]);
      #pragma unroll
      for(int o=16;o;o>>=1) s+=__shfl_xor_sync(0xffffffffu,s,o);
      if(lane==0) rsum[rr]=s;
    }
  }
  int start=argmax62(rsum,redv,redi);
  if(tid<62) md[tid]=D[start*62+tid];
  if(tid==0) idx5[0]=start;
  for(int it=1;it<NCL;it++){
    int far=argmax62(md,redv,redi);
    if(tid<62) md[tid]=fminf(md[tid],D[far*62+tid]);
    if(tid==0) idx5[it]=far;
  }
  __syncthreads();
  if(tid<NCL*3){ int k=tid/3,d=tid%3; cen[tid]=pos[idx5[k]*3+d]; }
  __syncthreads();
  float ls[20];
  #pragma unroll
  for(int j=0;j<20;j++) ls[j]=0;
  for(int e=tid;e<BB*CC;e+=256){
    int a=g_tempassign[e];
    float x0=pos_emb[(size_t)e*3], x1=pos_emb[(size_t)e*3+1], x2=pos_emb[(size_t)e*3+2];
    ls[a*3+0]+=x0; ls[a*3+1]+=x1; ls[a*3+2]+=x2; ls[15+a]+=1.0f;
  }
  #pragma unroll
  for(int j=0;j<20;j++) redp[tid*20+j]=ls[j];
  __syncthreads();
  for(int s=128;s>0;s>>=1){
    if(tid<s){ for(int j=0;j<20;j++) redp[tid*20+j]+=redp[(tid+s)*20+j]; }
    __syncthreads();
  }
  if(tid<NCL*3){ int k=tid/3,d=tid%3;
    float cnt=redp[15+k];
    avg[tid]= (cnt>0.0f) ? redp[k*3+d]/fmaxf(cnt,1.0f) : 0.0f;
  }
  __syncthreads();
  if(tid==0){
    float nc[NCL*3];
    for(int i=0;i<NCL;i++){
      float best=3.4e38f; int bj=0;
      for(int j=0;j<NCL;j++){
        float d2=0;
        for(int d=0;d<3;d++){ float df=cen[i*3+d]-avg[j*3+d]; d2+=df*df; }
        if(d2<best){best=d2;bj=j;}
      }
      for(int d=0;d<3;d++) nc[i*3+d]=0.8f*cen[i*3+d]+0.2f*avg[bj*3+d];
    }
    for(int j=0;j<15;j++) cen[j]=nc[j];
  }
  __syncthreads();
  if(tid<62){
    float dv[NCL]; int oi[NCL];
    for(int k=0;k<NCL;k++){
      float d2=0;
      for(int d=0;d<3;d++){ float df=pos[tid*3+d]-cen[k*3+d]; d2+=df*df; }
      dv[k]=d2; oi[k]=k;
    }
    for(int a=1;a<NCL;a++){
      float v=dv[a]; int vi=oi[a]; int bq=a-1;
      while(bq>=0 && dv[bq]>v){ dv[bq+1]=dv[bq]; oi[bq+1]=oi[bq]; bq--; }
      dv[bq+1]=v; oi[bq+1]=vi;
    }
    for(int k=0;k<NCL;k++) order[tid*NCL+k]=oi[k];
  }
  __syncthreads();
  if(tid==0){
    int counts[NCL]={0,0,0,0,0};
    const int sizes[NCL]={13,13,12,12,12};
    for(int c=0;c<62;c++){
      int cl=order[c*NCL+0];
      for(int r=0;r<NCL;r++){ int k=order[c*NCL+r]; if(counts[k]<sizes[k]){ cl=k; break; } }
      counts[cl]++; g_assign[c]=cl;
    }
  }
}

__device__ __forceinline__ void ln5b(const float* src, float* dst,
    const float* g, const float* bb, int tid){
  int wp=tid>>5, lane=tid&31;
  if(wp<5){
    int r=wp;
    float v0=src[r*128+lane],v1=src[r*128+lane+32],v2=src[r*128+lane+64],v3=src[r*128+lane+96];
    float s=v0+v1+v2+v3;
    #pragma unroll
    for(int o=16;o;o>>=1) s+=__shfl_xor_sync(0xffffffffu,s,o);
    float m=s*0.0078125f;
    float d0=v0-m,d1=v1-m,d2=v2-m,d3=v3-m;
    float q=d0*d0+d1*d1+d2*d2+d3*d3;
    #pragma unroll
    for(int o=16;o;o>>=1) q+=__shfl_xor_sync(0xffffffffu,q,o);
    float rstd=rsqrtf(q*0.0078125f+1e-5f);
    dst[r*128+lane]   =fmaf(d0*rstd,g[lane],bb[lane]);
    dst[r*128+lane+32]=fmaf(d1*rstd,g[lane+32],bb[lane+32]);
    dst[r*128+lane+64]=fmaf(d2*rstd,g[lane+64],bb[lane+64]);
    dst[r*128+lane+96]=fmaf(d3*rstd,g[lane+96],bb[lane+96]);
  }
}

// ---- transformer with fused token aggregation prologue (256 threads) ----
// GEMM k-loops use float4 smem operand loads: per 4 k's, 5 LDS.128 + 4 LDG + 20 FMA.
__global__ __launch_bounds__(256) void k_tr(const float* __restrict__ pos_enc,
    const float* __restrict__ bqkv,
    const float* __restrict__ bo, const float* __restrict__ b1, const float* __restrict__ b2,
    const float* __restrict__ ln1g, const float* __restrict__ ln1b,
    const float* __restrict__ ln2g, const float* __restrict__ ln2b,
    float* __restrict__ out){
  __shared__ float h[5*128];
  __shared__ float qkv[5*384];
  __shared__ float att[4*25];
  __shared__ float tmp[5*256];
  __shared__ int asg[62];
  int b=blockIdx.x, tid=threadIdx.x;
  float* hb = out + (size_t)b*5*128;
  int part=tid>>7, pr=tid&127;
  if(tid<62) asg[tid]=g_assign[tid];
  __syncthreads();
  {
    float a0=0,a1=0,a2=0,a3=0,a4=0;
    const float* pf=&g_pf[((size_t)b*62)*128];
    int c0=part?31:0, c1=part?62:31;
    for(int c=c0;c<c1;c++){
      float v=pf[(size_t)c*128+pr];
      int k=asg[c];
      a0+=(k==0)?v:0.0f; a1+=(k==1)?v:0.0f; a2+=(k==2)?v:0.0f;
      a3+=(k==3)?v:0.0f; a4+=(k==4)?v:0.0f;
    }
    tmp[part*640+0*128+pr]=a0; tmp[part*640+1*128+pr]=a1; tmp[part*640+2*128+pr]=a2;
    tmp[part*640+3*128+pr]=a3; tmp[part*640+4*128+pr]=a4;
  }
  __syncthreads();
  {
    const float szs[NCL]={13.0f,13.0f,12.0f,12.0f,12.0f};
    for(int i=tid;i<640;i+=256){
      int k=i>>7;
      h[i]=(tmp[i]+tmp[640+i])/szs[k]+pos_enc[i];
    }
  }
  __syncthreads();
  for(int l=0;l<3;l++){
    {
      const float* W=&g_WqkvT[(size_t)l*128*384];
      #pragma unroll
      for(int pass=0;pass<2;pass++){
        int col = pass? 256+tid : tid;
        if(pass==0 || tid<128){
          float bv=bqkv[l*384+col];
          float a0=bv,a1=bv,a2=bv,a3=bv,a4=bv;
          #pragma unroll 4
          for(int k=0;k<128;k+=4){
            float w0=W[k*384+col], w1=W[(k+1)*384+col], w2=W[(k+2)*384+col], w3=W[(k+3)*384+col];
            float4 h0=*(const float4*)&h[k];
            float4 h1=*(const float4*)&h[128+k];
            float4 h2=*(const float4*)&h[256+k];
            float4 h3=*(const float4*)&h[384+k];
            float4 h4=*(const float4*)&h[512+k];
            a0=fmaf(h0.x,w0,a0); a0=fmaf(h0.y,w1,a0); a0=fmaf(h0.z,w2,a0); a0=fmaf(h0.w,w3,a0);
            a1=fmaf(h1.x,w0,a1); a1=fmaf(h1.y,w1,a1); a1=fmaf(h1.z,w2,a1); a1=fmaf(h1.w,w3,a1);
            a2=fmaf(h2.x,w0,a2); a2=fmaf(h2.y,w1,a2); a2=fmaf(h2.z,w2,a2); a2=fmaf(h2.w,w3,a2);
            a3=fmaf(h3.x,w0,a3); a3=fmaf(h3.y,w1,a3); a3=fmaf(h3.z,w2,a3); a3=fmaf(h3.w,w3,a3);
            a4=fmaf(h4.x,w0,a4); a4=fmaf(h4.y,w1,a4); a4=fmaf(h4.z,w2,a4); a4=fmaf(h4.w,w3,a4);
          }
          qkv[0*384+col]=a0; qkv[1*384+col]=a1; qkv[2*384+col]=a2;
          qkv[3*384+col]=a3; qkv[4*384+col]=a4;
        }
      }
    }
    __syncthreads();
    if(tid<100){
      int hd=tid/25, r=tid%25, qt=r/5, kt=r%5;
      float s=0;
      const float* qp=&qkv[qt*384+hd*32];
      const float* kp=&qkv[kt*384+128+hd*32];
      #pragma unroll 8
      for(int d=0;d<32;d++) s=fmaf(qp[d],kp[d],s);
      att[hd*25+qt*5+kt]=s*0.17677669529663689f;
    }
    __syncthreads();
    if(tid<20){
      int hd=tid/5, qt=tid%5;
      float* a=&att[hd*25+qt*5];
      float m=a[0]; for(int i=1;i<5;i++) m=fmaxf(m,a[i]);
      float e[5], s=0;
      for(int i=0;i<5;i++){ e[i]=expf(a[i]-m); s+=e[i]; }
      float inv=1.0f/s;
      for(int i=0;i<5;i++) a[i]=e[i]*inv;
    }
    __syncthreads();
    {
      int hd=pr/32, d=pr%32;
      int q0=part?3:0, q1=part?5:3;
      for(int qt=q0;qt<q1;qt++){
        float s=0;
        #pragma unroll
        for(int kt=0;kt<5;kt++) s=fmaf(att[hd*25+qt*5+kt], qkv[kt*384+256+hd*32+d], s);
        tmp[qt*128+pr]=s;
      }
    }
    __syncthreads();
    {
      const float* W=&g_WoT[(size_t)l*128*128];
      float bv=bo[l*128+pr];
      if(part==0){
        float a0=bv,a1=bv,a2=bv;
        #pragma unroll 4
        for(int k=0;k<128;k+=4){
          float w0=W[k*128+pr], w1=W[(k+1)*128+pr], w2=W[(k+2)*128+pr], w3=W[(k+3)*128+pr];
          float4 t0=*(const float4*)&tmp[k];
          float4 t1=*(const float4*)&tmp[128+k];
          float4 t2=*(const float4*)&tmp[256+k];
          a0=fmaf(t0.x,w0,a0); a0=fmaf(t0.y,w1,a0); a0=fmaf(t0.z,w2,a0); a0=fmaf(t0.w,w3,a0);
          a1=fmaf(t1.x,w0,a1); a1=fmaf(t1.y,w1,a1); a1=fmaf(t1.z,w2,a1); a1=fmaf(t1.w,w3,a1);
          a2=fmaf(t2.x,w0,a2); a2=fmaf(t2.y,w1,a2); a2=fmaf(t2.z,w2,a2); a2=fmaf(t2.w,w3,a2);
        }
        qkv[pr]=h[pr]+a0; qkv[128+pr]=h[128+pr]+a1; qkv[256+pr]=h[256+pr]+a2;
      }else{
        float a3=bv,a4=bv;
        #pragma unroll 4
        for(int k=0;k<128;k+=4){
          float w0=W[k*128+pr], w1=W[(k+1)*128+pr], w2=W[(k+2)*128+pr], w3=W[(k+3)*128+pr];
          float4 t3=*(const float4*)&tmp[384+k];
          float4 t4=*(const float4*)&tmp[512+k];
          a3=fmaf(t3.x,w0,a3); a3=fmaf(t3.y,w1,a3); a3=fmaf(t3.z,w2,a3); a3=fmaf(t3.w,w3,a3);
          a4=fmaf(t4.x,w0,a4); a4=fmaf(t4.y,w1,a4); a4=fmaf(t4.z,w2,a4); a4=fmaf(t4.w,w3,a4);
        }
        qkv[384+pr]=h[384+pr]+a3; qkv[512+pr]=h[512+pr]+a4;
      }
    }
    __syncthreads();
    ln5b(qkv,h,ln1g+l*128,ln1b+l*128,tid);
    __syncthreads();
    {
      const float* W=&g_W1T[(size_t)l*128*256];
      float bv=b1[l*256+tid];
      float a0=bv,a1=bv,a2=bv,a3=bv,a4=bv;
      #pragma unroll 4
      for(int k=0;k<128;k+=4){
        float w0=W[k*256+tid], w1=W[(k+1)*256+tid], w2=W[(k+2)*256+tid], w3=W[(k+3)*256+tid];
        float4 h0=*(const float4*)&h[k];
        float4 h1=*(const float4*)&h[128+k];
        float4 h2=*(const float4*)&h[256+k];
        float4 h3=*(const float4*)&h[384+k];
        float4 h4=*(const float4*)&h[512+k];
        a0=fmaf(h0.x,w0,a0); a0=fmaf(h0.y,w1,a0); a0=fmaf(h0.z,w2,a0); a0=fmaf(h0.w,w3,a0);
        a1=fmaf(h1.x,w0,a1); a1=fmaf(h1.y,w1,a1); a1=fmaf(h1.z,w2,a1); a1=fmaf(h1.w,w3,a1);
        a2=fmaf(h2.x,w0,a2); a2=fmaf(h2.y,w1,a2); a2=fmaf(h2.z,w2,a2); a2=fmaf(h2.w,w3,a2);
        a3=fmaf(h3.x,w0,a3); a3=fmaf(h3.y,w1,a3); a3=fmaf(h3.z,w2,a3); a3=fmaf(h3.w,w3,a3);
        a4=fmaf(h4.x,w0,a4); a4=fmaf(h4.y,w1,a4); a4=fmaf(h4.z,w2,a4); a4=fmaf(h4.w,w3,a4);
      }
      tmp[0*256+tid]=fmaxf(a0,0.0f); tmp[1*256+tid]=fmaxf(a1,0.0f);
      tmp[2*256+tid]=fmaxf(a2,0.0f); tmp[3*256+tid]=fmaxf(a3,0.0f);
      tmp[4*256+tid]=fmaxf(a4,0.0f);
    }
    __syncthreads();
    {
      const float* W=&g_W2T[(size_t)l*256*128];
      float bv=b2[l*128+pr];
      if(part==0){
        float a0=bv,a1=bv,a2=bv;
        #pragma unroll 4
        for(int k=0;k<256;k+=4){
          float w0=W[k*128+pr], w1=W[(k+1)*128+pr], w2=W[(k+2)*128+pr], w3=W[(k+3)*128+pr];
          float4 t0=*(const float4*)&tmp[k];
          float4 t1=*(const float4*)&tmp[256+k];
          float4 t2=*(const float4*)&tmp[512+k];
          a0=fmaf(t0.x,w0,a0); a0=fmaf(t0.y,w1,a0); a0=fmaf(t0.z,w2,a0); a0=fmaf(t0.w,w3,a0);
          a1=fmaf(t1.x,w0,a1); a1=fmaf(t1.y,w1,a1); a1=fmaf(t1.z,w2,a1); a1=fmaf(t1.w,w3,a1);
          a2=fmaf(t2.x,w0,a2); a2=fmaf(t2.y,w1,a2); a2=fmaf(t2.z,w2,a2); a2=fmaf(t2.w,w3,a2);
        }
        qkv[pr]=h[pr]+a0; qkv[128+pr]=h[128+pr]+a1; qkv[256+pr]=h[256+pr]+a2;
      }else{
        float a3=bv,a4=bv;
        #pragma unroll 4
        for(int k=0;k<256;k+=4){
          float w0=W[k*128+pr], w1=W[(k+1)*128+pr], w2=W[(k+2)*128+pr], w3=W[(k+3)*128+pr];
          float4 t3=*(const float4*)&tmp[768+k];
          float4 t4=*(const float4*)&tmp[1024+k];
          a3=fmaf(t3.x,w0,a3); a3=fmaf(t3.y,w1,a3); a3=fmaf(t3.z,w2,a3); a3=fmaf(t3.w,w3,a3);
          a4=fmaf(t4.x,w0,a4); a4=fmaf(t4.y,w1,a4); a4=fmaf(t4.z,w2,a4); a4=fmaf(t4.w,w3,a4);
        }
        qkv[384+pr]=h[384+pr]+a3; qkv[512+pr]=h[512+pr]+a4;
      }
    }
    __syncthreads();
    ln5b(qkv,h,ln2g+l*128,ln2b+l*128,tid);
    __syncthreads();
  }
  for(int i=tid;i<640;i+=256) hb[i]=h[i];
}

extern "C" void kernel_launch(void* const* d_in, const int* in_sizes, int n_in,
                              void* d_out, int out_size){
  const float* x        =(const float*)d_in[0];
  const float* pos_emb  =(const float*)d_in[1];
  const float* proj_w   =(const float*)d_in[2];
  const float* proj_b   =(const float*)d_in[3];
  const float* proj_ln_g=(const float*)d_in[4];
  const float* proj_ln_b=(const float*)d_in[5];
  const float* pos_enc  =(const float*)d_in[6];
  const float* Wqkv     =(const float*)d_in[7];
  const float* bqkv     =(const float*)d_in[8];
  const float* Wo       =(const float*)d_in[9];
  const float* bo       =(const float*)d_in[10];
  const float* W1       =(const float*)d_in[11];
  const float* b1       =(const float*)d_in[12];
  const float* W2       =(const float*)d_in[13];
  const float* b2       =(const float*)d_in[14];
  const float* ln1_g    =(const float*)d_in[15];
  const float* ln1_b    =(const float*)d_in[16];
  const float* ln2_g    =(const float*)d_in[17];
  const float* ln2_b    =(const float*)d_in[18];
  float* out=(float*)d_out;
  k_init<<<192,256>>>(proj_w,Wqkv,Wo,W1,W2);
  k_feat<<<BB*CC,256>>>(x);
  k_projfps<<<128+BB*CC/32,256>>>(proj_b,proj_ln_g,proj_ln_b,pos_emb);
  k_cluster<<<1,256>>>(pos_emb);        // 4th launch: ncu capture lands here
  k_tr<<<BB,256>>>(pos_enc,bqkv,bo,b1,b2,ln1_g,ln1_b,ln2_g,ln2_b,out);
}

// round 17
// speedup vs baseline: 1.0617x; 1.0617x over previous
#include <cuda_runtime.h>
#include <math.h>

#define BB 128
#define CC 62
#define LL 2000
#define NW 36
#define DMM 128
#define NCL 5

__device__ float g_feats[BB*CC*504];
__device__ float g_pf[BB*CC*DMM];
__device__ float g_projWT[504*DMM];
__device__ float g_WqkvT[3*DMM*384];
__device__ float g_WoT[3*DMM*DMM];
__device__ float g_W1T[3*DMM*256];
__device__ float g_W2T[3*256*DMM];
__device__ float g_B50[52*96];
__device__ int   g_tempassign[BB*CC];
__device__ int   g_assign[CC];
__device__ int   g_fpsdone = 0;

__global__ void k_init(const float* __restrict__ proj_w, const float* __restrict__ Wqkv,
                       const float* __restrict__ Wo, const float* __restrict__ W1,
                       const float* __restrict__ W2){
  int stride = gridDim.x*blockDim.x;
  int t0 = blockIdx.x*blockDim.x + threadIdx.x;
  if(t0==0) g_fpsdone=0;
  for (int t=t0; t<52*96; t+=stride){
    int m=t/96, c=t%96, f=c>>1;
    float v=0.0f;
    if(m<50 && c<92){
      double ang = 6.283185307179586476925286766559 * (double)(f*m) / 250.0;
      v = (c&1)? (float)(-sin(ang)) : (float)cos(ang);
    }
    g_B50[t]=v;
  }
  for (int t=t0; t<504*DMM; t+=stride){ int k=t/DMM, j=t%DMM; g_projWT[t]=proj_w[j*504+k]; }
  for (int t=t0; t<3*DMM*384; t+=stride){ int l=t/(DMM*384); int r=t%(DMM*384); int k=r/384, j=r%384;
    g_WqkvT[t]=Wqkv[((size_t)l*384+j)*DMM+k]; }
  for (int t=t0; t<3*DMM*DMM; t+=stride){ int l=t/(DMM*DMM); int r=t%(DMM*DMM); int k=r/DMM, j=r%DMM;
    g_WoT[t]=Wo[((size_t)l*DMM+j)*DMM+k]; }
  for (int t=t0; t<3*DMM*256; t+=stride){ int l=t/(DMM*256); int r=t%(DMM*256); int k=r/256, j=r%256;
    g_W1T[t]=W1[((size_t)l*256+j)*DMM+k]; }
  for (int t=t0; t<3*256*DMM; t+=stride){ int l=t/(256*DMM); int r=t%(256*DMM); int k=r/DMM, j=r%DMM;
    g_W2T[t]=W2[((size_t)l*DMM+j)*256+k]; }
}

__device__ __forceinline__ int argmax62(const float* vals, float* redv, int* redi){
  int tid=threadIdx.x;
  __syncthreads();
  float v=(tid<62)?vals[tid]:-3.4e38f;
  int idx=tid;
  #pragma unroll
  for(int o=16;o;o>>=1){
    float ov=__shfl_xor_sync(0xffffffffu,v,o);
    int oi=__shfl_xor_sync(0xffffffffu,idx,o);
    if(ov>v || (ov==v && oi<idx)){ v=ov; idx=oi; }
  }
  if((tid&31)==0){ redv[tid>>5]=v; redi[tid>>5]=idx; }
  __syncthreads();
  float bv=redv[0]; int bi=redi[0];
  if(redv[1]>bv || (redv[1]==bv && redi[1]<bi)){ bv=redv[1]; bi=redi[1]; }
  return bi;
}

// ---- features: segment DFT (4x4 tile, spill-free @48 regs, 5 blocks/SM) ----
__global__ __launch_bounds__(256,5) void k_feat(const float* __restrict__ x){
  __shared__ float sA[40*52];
  __shared__ float sB[52*96];
  __shared__ float sP[40*96];
  __shared__ float wtab25[50];
  int bc = blockIdx.x, tid = threadIdx.x;
  const float* xr = x + (size_t)bc*LL;
  for (int i=tid;i<40*52;i+=256){ int s=i/52,m=i%52; sA[i]=(m<50)? xr[s*50+m] : 0.0f; }
  for (int i=tid;i<52*96;i+=256) sB[i]=g_B50[i];
  if (tid<25){
    int fm=tid/5, j=tid%5;
    int m5=(fm*j)%5;
    float ang = 6.2831853071795864769f * (float)m5 / 5.0f;
    wtab25[tid*2]=cosf(ang); wtab25[tid*2+1]=-sinf(ang);
  }
  __syncthreads();
  if (tid<240){
    int sg=tid/24, cg=tid%24;
    float acc[4][4];
    #pragma unroll
    for(int r=0;r<4;r++){ acc[r][0]=0;acc[r][1]=0;acc[r][2]=0;acc[r][3]=0; }
    const float* A0=&sA[(sg*4+0)*52];
    const float* A1=&sA[(sg*4+1)*52];
    const float* A2=&sA[(sg*4+2)*52];
    const float* A3=&sA[(sg*4+3)*52];
    #pragma unroll 1
    for(int k=0;k<52;k+=4){
      float4 a0=*(const float4*)&A0[k];
      float4 a1=*(const float4*)&A1[k];
      float4 a2=*(const float4*)&A2[k];
      float4 a3=*(const float4*)&A3[k];
      #pragma unroll
      for(int kk=0;kk<4;kk++){
        float4 bv=*(const float4*)&sB[(k+kk)*96+cg*4];
        float e0=kk==0?a0.x:kk==1?a0.y:kk==2?a0.z:a0.w;
        float e1=kk==0?a1.x:kk==1?a1.y:kk==2?a1.z:a1.w;
        float e2=kk==0?a2.x:kk==1?a2.y:kk==2?a2.z:a2.w;
        float e3=kk==0?a3.x:kk==1?a3.y:kk==2?a3.z:a3.w;
        acc[0][0]=fmaf(e0,bv.x,acc[0][0]); acc[0][1]=fmaf(e0,bv.y,acc[0][1]);
        acc[0][2]=fmaf(e0,bv.z,acc[0][2]); acc[0][3]=fmaf(e0,bv.w,acc[0][3]);
        acc[1][0]=fmaf(e1,bv.x,acc[1][0]); acc[1][1]=fmaf(e1,bv.y,acc[1][1]);
        acc[1][2]=fmaf(e1,bv.z,acc[1][2]); acc[1][3]=fmaf(e1,bv.w,acc[1][3]);
        acc[2][0]=fmaf(e2,bv.x,acc[2][0]); acc[2][1]=fmaf(e2,bv.y,acc[2][1]);
        acc[2][2]=fmaf(e2,bv.z,acc[2][2]); acc[2][3]=fmaf(e2,bv.w,acc[2][3]);
        acc[3][0]=fmaf(e3,bv.x,acc[3][0]); acc[3][1]=fmaf(e3,bv.y,acc[3][1]);
        acc[3][2]=fmaf(e3,bv.z,acc[3][2]); acc[3][3]=fmaf(e3,bv.w,acc[3][3]);
      }
    }
    #pragma unroll
    for(int r=0;r<4;r++)
      *(float4*)&sP[(sg*4+r)*96 + cg*4] = make_float4(acc[r][0],acc[r][1],acc[r][2],acc[r][3]);
  }
  __syncthreads();
  float* Y = sB;
  for(int t=tid;t<NW*46;t+=256){
    int w=t/46, f=t%46, fm=f%5;
    const float* wt=&wtab25[fm*10];
    float yre=0, yim=0;
    #pragma unroll
    for(int j=0;j<5;j++){
      float wr=wt[j*2], wi=wt[j*2+1];
      float pr=sP[(w+j)*96+2*f], pi=sP[(w+j)*96+2*f+1];
      yre=fmaf(wr,pr,yre); yre=fmaf(-wi,pi,yre);
      yim=fmaf(wr,pi,yim); yim=fmaf(wi,pr,yim);
    }
    Y[w*92+2*f]=yre; Y[w*92+2*f+1]=yim;
  }
  __syncthreads();
  float* ps = sA;
  for(int t=tid;t<NW*44;t+=256){
    int w=t/44, fi=t%44, f=fi+1;
    float xre=0.5f*Y[w*92+2*f]   - 0.25f*(Y[w*92+2*(f-1)]   + Y[w*92+2*(f+1)]);
    float xim=0.5f*Y[w*92+2*f+1] - 0.25f*(Y[w*92+2*(f-1)+1] + Y[w*92+2*(f+1)+1]);
    ps[w*44+fi]=(xre*xre+xim*xim)*(1.0f/250.0f);
  }
  __syncthreads();
  const int blo[7]={1,4,8,12,16,20,30};
  const int bhi[7]={4,8,12,16,20,30,45};
  float vp=0.0f, vd=0.0f;
  if (tid<252){
    int w=tid/7,bd=tid%7;
    float s=0;
    for(int f=blo[bd];f<bhi[bd];f++) s+=ps[w*44+f-1];
    vp=s/(float)(bhi[bd]-blo[bd]);
    vd=0.5f*logf(17.079468445347132f*vp+1e-9f);
  }
  float4 r; r.x=vp; r.y=vp*vp; r.z=vd; r.w=vd*vd;
  #pragma unroll
  for(int o=16;o;o>>=1){
    r.x+=__shfl_xor_sync(0xffffffffu,r.x,o);
    r.y+=__shfl_xor_sync(0xffffffffu,r.y,o);
    r.z+=__shfl_xor_sync(0xffffffffu,r.z,o);
    r.w+=__shfl_xor_sync(0xffffffffu,r.w,o);
  }
  float4* red4=(float4*)sP;
  if((tid&31)==0) red4[tid>>5]=r;
  __syncthreads();
  float4 t4=red4[0];
  #pragma unroll
  for(int w=1;w<8;w++){ float4 q=red4[w]; t4.x+=q.x; t4.y+=q.y; t4.z+=q.z; t4.w+=q.w; }
  float mp=t4.x*(1.0f/252.0f);
  float sdp=sqrtf(fmaxf(t4.y-252.0f*mp*mp,0.0f)*(1.0f/251.0f));
  float md_=t4.z*(1.0f/252.0f);
  float sdd=sqrtf(fmaxf(t4.w-252.0f*md_*md_,0.0f)*(1.0f/251.0f));
  if(tid<252){
    int w=tid/7,bd=tid%7;
    size_t base=(size_t)bc*504;
    g_feats[base + w*14 + bd]     =(vp-mp)/(sdp+1e-9f);
    g_feats[base + w*14 + 7 + bd] =(vd-md_)/(sdd+1e-9f);
  }
}

// ---- FUSED: fps (0..127) + proj 32-row tiles (128..375) + cluster (376) ----
union SmemU {
  struct { float sAT[56*36]; float sW[56*128]; } proj;
  struct { float G[62*62]; float tileT[84*68]; float rsum[62]; float md[62]; float nrm[62];
           float redv[8]; float cc[NCL*3]; float ncc[NCL]; int redi[8]; int idx5[NCL]; } fps;
  struct { float pos[62*3]; float D[62*62]; float nrm[62]; float rsum[62]; float md[62];
           float redv[8]; float cen[NCL*3]; float redp[256*20]; float avg[NCL*3];
           int redi[8]; int idx5[NCL]; int order[62*NCL]; } clu;
};

__global__ __launch_bounds__(256) void k_projfps(const float* __restrict__ proj_b,
    const float* __restrict__ lng, const float* __restrict__ lnb,
    const float* __restrict__ pos_emb){
  __shared__ SmemU u;
  int tid=threadIdx.x;
  if(blockIdx.x>=128 && blockIdx.x<376){
    // ================= PROJ =================
    float* sAT=u.proj.sAT;
    float* sW=u.proj.sW;
    int tr=tid>>5, tc=tid&31;
    int row0=(blockIdx.x-128)*32;
    float acc[4][4];
    {
      float4 pb=*(const float4*)&proj_b[4*tc];
      #pragma unroll
      for(int r=0;r<4;r++){ acc[r][0]=pb.x; acc[r][1]=pb.y; acc[r][2]=pb.z; acc[r][3]=pb.w; }
    }
    for(int kc=0;kc<504;kc+=56){
      #pragma unroll 4
      for(int i=tid;i<56*32;i+=256){ int k=i%56, r=i/56;
        sAT[k*36+r]=g_feats[(size_t)(row0+r)*504+kc+k]; }
      #pragma unroll 4
      for(int i=tid;i<56*128;i+=256) sW[i]=g_projWT[(size_t)(kc+(i>>7))*128+(i&127)];
      __syncthreads();
      #pragma unroll 4
      for(int k=0;k<56;k++){
        float4 a0=*(const float4*)&sAT[k*36+4*tr];
        float4 w =*(const float4*)&sW[k*128+4*tc];
        acc[0][0]=fmaf(a0.x,w.x,acc[0][0]); acc[0][1]=fmaf(a0.x,w.y,acc[0][1]); acc[0][2]=fmaf(a0.x,w.z,acc[0][2]); acc[0][3]=fmaf(a0.x,w.w,acc[0][3]);
        acc[1][0]=fmaf(a0.y,w.x,acc[1][0]); acc[1][1]=fmaf(a0.y,w.y,acc[1][1]); acc[1][2]=fmaf(a0.y,w.z,acc[1][2]); acc[1][3]=fmaf(a0.y,w.w,acc[1][3]);
        acc[2][0]=fmaf(a0.z,w.x,acc[2][0]); acc[2][1]=fmaf(a0.z,w.y,acc[2][1]); acc[2][2]=fmaf(a0.z,w.z,acc[2][2]); acc[2][3]=fmaf(a0.z,w.w,acc[2][3]);
        acc[3][0]=fmaf(a0.w,w.x,acc[3][0]); acc[3][1]=fmaf(a0.w,w.y,acc[3][1]); acc[3][2]=fmaf(a0.w,w.z,acc[3][2]); acc[3][3]=fmaf(a0.w,w.w,acc[3][3]);
      }
      __syncthreads();
    }
    float4 g=*(const float4*)&lng[4*tc];
    float4 bb=*(const float4*)&lnb[4*tc];
    #pragma unroll
    for(int r=0;r<4;r++){
      float s=acc[r][0]+acc[r][1]+acc[r][2]+acc[r][3];
      #pragma unroll
      for(int o=16;o;o>>=1) s+=__shfl_xor_sync(0xffffffffu,s,o);
      float m=s*(1.0f/128.0f);
      float d0=acc[r][0]-m,d1=acc[r][1]-m,d2=acc[r][2]-m,d3=acc[r][3]-m;
      float q=d0*d0+d1*d1+d2*d2+d3*d3;
      #pragma unroll
      for(int o=16;o;o>>=1) q+=__shfl_xor_sync(0xffffffffu,q,o);
      float rstd=rsqrtf(q*(1.0f/128.0f)+1e-5f);
      float4 o4;
      o4.x=fmaxf(fmaf(d0*rstd,g.x,bb.x),0.0f);
      o4.y=fmaxf(fmaf(d1*rstd,g.y,bb.y),0.0f);
      o4.z=fmaxf(fmaf(d2*rstd,g.z,bb.z),0.0f);
      o4.w=fmaxf(fmaf(d3*rstd,g.w,bb.w),0.0f);
      *(float4*)&g_pf[(size_t)(row0+4*tr+r)*128+4*tc]=o4;
    }
  } else if(blockIdx.x<128) {
    // ================= FPS =================
    float* G=u.fps.G;
    float* tileT=u.fps.tileT;
    float* rsum=u.fps.rsum;
    float* md=u.fps.md;
    float* nrm=u.fps.nrm;
    float* redv=u.fps.redv;
    int*   redi=u.fps.redi;
    int*   idx5=u.fps.idx5;
    float* cc=u.fps.cc;
    float* ncc=u.fps.ncc;
    int b=blockIdx.x;
    int tr=tid>>4, tc=tid&15;
    float acc[4][4];
    #pragma unroll
    for(int r=0;r<4;r++){ acc[r][0]=0;acc[r][1]=0;acc[r][2]=0;acc[r][3]=0; }
    for(int c0=0;c0<504;c0+=84){
      #pragma unroll 4
      for(int i=tid;i<84*64;i+=256){ int r=i/84, k=i%84;
        tileT[k*68+r]=(r<62)? g_feats[((size_t)b*62+r)*504+c0+k] : 0.0f; }
      __syncthreads();
      #pragma unroll 4
      for(int k=0;k<84;k++){
        float4 av=*(const float4*)&tileT[k*68+4*tr];
        float4 bv=*(const float4*)&tileT[k*68+4*tc];
        acc[0][0]=fmaf(av.x,bv.x,acc[0][0]); acc[0][1]=fmaf(av.x,bv.y,acc[0][1]); acc[0][2]=fmaf(av.x,bv.z,acc[0][2]); acc[0][3]=fmaf(av.x,bv.w,acc[0][3]);
        acc[1][0]=fmaf(av.y,bv.x,acc[1][0]); acc[1][1]=fmaf(av.y,bv.y,acc[1][1]); acc[1][2]=fmaf(av.y,bv.z,acc[1][2]); acc[1][3]=fmaf(av.y,bv.w,acc[1][3]);
        acc[2][0]=fmaf(av.z,bv.x,acc[2][0]); acc[2][1]=fmaf(av.z,bv.y,acc[2][1]); acc[2][2]=fmaf(av.z,bv.z,acc[2][2]); acc[2][3]=fmaf(av.z,bv.w,acc[2][3]);
        acc[3][0]=fmaf(av.w,bv.x,acc[3][0]); acc[3][1]=fmaf(av.w,bv.y,acc[3][1]); acc[3][2]=fmaf(av.w,bv.z,acc[3][2]); acc[3][3]=fmaf(av.w,bv.w,acc[3][3]);
      }
      __syncthreads();
    }
    #pragma unroll
    for(int r=0;r<4;r++){
      int gr=4*tr+r;
      if(gr<62){
        #pragma unroll
        for(int c=0;c<4;c++){
          int gc=4*tc+c;
          if(gc<62) G[gr*62+gc]=acc[r][c];
        }
      }
    }
    __syncthreads();
    if(tid<62) nrm[tid]=G[tid*62+tid];
    __syncthreads();
    for(int p=tid;p<3844;p+=256){ int i=p/62,j=p%62; G[p]=fmaxf(nrm[i]+nrm[j]-2.0f*G[p],0.0f); }
    __syncthreads();
    {
      int w=tid>>5, lane=tid&31;
      for(int rr=w;rr<62;rr+=8){
        float s=sqrtf(G[rr*62+lane]);
        if(lane+32<62) s+=sqrtf(G[rr*62+lane+32]);
        #pragma unroll
        for(int o=16;o;o>>=1) s+=__shfl_xor_sync(0xffffffffu,s,o);
        if(lane==0) rsum[rr]=s;
      }
    }
    int start=argmax62(rsum,redv,redi);
    if(tid<62) md[tid]=G[start*62+tid];
    if(tid==0) idx5[0]=start;
    for(int it=1;it<NCL;it++){
      int far=argmax62(md,redv,redi);
      if(tid<62) md[tid]=fminf(md[tid],G[far*62+tid]);
      if(tid==0) idx5[it]=far;
    }
    __syncthreads();
    if(tid<NCL*3){ int k=tid/3,d=tid%3; cc[tid]=pos_emb[((size_t)b*62+idx5[k])*3+d]; }
    __syncthreads();
    if(tid<NCL){ float s=0; for(int d=0;d<3;d++) s+=cc[tid*3+d]*cc[tid*3+d]; ncc[tid]=s; }
    __syncthreads();
    if(tid<62){
      float p0=pos_emb[((size_t)b*62+tid)*3+0];
      float p1=pos_emb[((size_t)b*62+tid)*3+1];
      float p2=pos_emb[((size_t)b*62+tid)*3+2];
      float np=p0*p0+p1*p1+p2*p2;
      float best=3.4e38f; int bi=0;
      for(int k=0;k<NCL;k++){
        float dot=p0*cc[k*3]+p1*cc[k*3+1]+p2*cc[k*3+2];
        float d2=fmaxf(np+ncc[k]-2.0f*dot,0.0f);
        if(d2<best){best=d2;bi=k;}
      }
      g_tempassign[b*62+tid]=bi;
    }
    // signal completion
    __syncthreads();
    __threadfence();
    if(tid==0) atomicAdd(&g_fpsdone,1);
  } else {
    // ================= CLUSTER (block 376) =================
    float* pos=u.clu.pos;
    float* D=u.clu.D;
    float* nrm=u.clu.nrm;
    float* rsum=u.clu.rsum;
    float* md=u.clu.md;
    float* redv=u.clu.redv;
    int*   redi=u.clu.redi;
    int*   idx5=u.clu.idx5;
    float* cen=u.clu.cen;
    float* redp=u.clu.redp;
    float* avg=u.clu.avg;
    int*   order=u.clu.order;
    if(tid<186) pos[tid]=pos_emb[tid];
    __syncthreads();
    if(tid<62){ float s=0; for(int d=0;d<3;d++) s+=pos[tid*3+d]*pos[tid*3+d]; nrm[tid]=s; }
    __syncthreads();
    for(int p=tid;p<3844;p+=256){ int i=p/62,j=p%62;
      float dot=pos[i*3]*pos[j*3]+pos[i*3+1]*pos[j*3+1]+pos[i*3+2]*pos[j*3+2];
      D[p]=fmaxf(nrm[i]+nrm[j]-2.0f*dot,0.0f); }
    __syncthreads();
    {
      int w=tid>>5, lane=tid&31;
      for(int rr=w;rr<62;rr+=8){
        float s=sqrtf(D[rr*62+lane]);
        if(lane+32<62) s+=sqrtf(D[rr*62+lane+32]);
        #pragma unroll
        for(int o=16;o;o>>=1) s+=__shfl_xor_sync(0xffffffffu,s,o);
        if(lane==0) rsum[rr]=s;
      }
    }
    int start=argmax62(rsum,redv,redi);
    if(tid<62) md[tid]=D[start*62+tid];
    if(tid==0) idx5[0]=start;
    for(int it=1;it<NCL;it++){
      int far=argmax62(md,redv,redi);
      if(tid<62) md[tid]=fminf(md[tid],D[far*62+tid]);
      if(tid==0) idx5[it]=far;
    }
    __syncthreads();
    if(tid<NCL*3){ int k=tid/3,d=tid%3; cen[tid]=pos[idx5[k]*3+d]; }
    // wait for all fps blocks to publish g_tempassign
    if(tid==0){ while(atomicAdd(&g_fpsdone,0)<128){} }
    __syncthreads();
    __threadfence();
    float ls[20];
    #pragma unroll
    for(int j=0;j<20;j++) ls[j]=0;
    for(int e=tid;e<BB*CC;e+=256){
      int a=g_tempassign[e];
      float x0=pos_emb[(size_t)e*3], x1=pos_emb[(size_t)e*3+1], x2=pos_emb[(size_t)e*3+2];
      ls[a*3+0]+=x0; ls[a*3+1]+=x1; ls[a*3+2]+=x2; ls[15+a]+=1.0f;
    }
    #pragma unroll
    for(int j=0;j<20;j++) redp[tid*20+j]=ls[j];
    __syncthreads();
    for(int s=128;s>0;s>>=1){
      if(tid<s){ for(int j=0;j<20;j++) redp[tid*20+j]+=redp[(tid+s)*20+j]; }
      __syncthreads();
    }
    if(tid<NCL*3){ int k=tid/3,d=tid%3;
      float cnt=redp[15+k];
      avg[tid]= (cnt>0.0f) ? redp[k*3+d]/fmaxf(cnt,1.0f) : 0.0f;
    }
    __syncthreads();
    if(tid==0){
      float nc[NCL*3];
      for(int i=0;i<NCL;i++){
        float best=3.4e38f; int bj=0;
        for(int j=0;j<NCL;j++){
          float d2=0;
          for(int d=0;d<3;d++){ float df=cen[i*3+d]-avg[j*3+d]; d2+=df*df; }
          if(d2<best){best=d2;bj=j;}
        }
        for(int d=0;d<3;d++) nc[i*3+d]=0.8f*cen[i*3+d]+0.2f*avg[bj*3+d];
      }
      for(int j=0;j<15;j++) cen[j]=nc[j];
    }
    __syncthreads();
    if(tid<62){
      float dv[NCL]; int oi[NCL];
      for(int k=0;k<NCL;k++){
        float d2=0;
        for(int d=0;d<3;d++){ float df=pos[tid*3+d]-cen[k*3+d]; d2+=df*df; }
        dv[k]=d2; oi[k]=k;
      }
      for(int a=1;a<NCL;a++){
        float v=dv[a]; int vi=oi[a]; int bq=a-1;
        while(bq>=0 && dv[bq]>v){ dv[bq+1]=dv[bq]; oi[bq+1]=oi[bq]; bq--; }
        dv[bq+1]=v; oi[bq+1]=vi;
      }
      for(int k=0;k<NCL;k++) order[tid*NCL+k]=oi[k];
    }
    __syncthreads();
    if(tid==0){
      int counts[NCL]={0,0,0,0,0};
      const int sizes[NCL]={13,13,12,12,12};
      for(int c=0;c<62;c++){
        int cl=order[c*NCL+0];
        for(int r=0;r<NCL;r++){ int k=order[c*NCL+r]; if(counts[k]<sizes[k]){ cl=k; break; } }
        counts[cl]++; g_assign[c]=cl;
      }
    }
  }
}

__device__ __forceinline__ void ln5b(const float* src, float* dst,
    const float* g, const float* bb, int tid){
  int wp=tid>>5, lane=tid&31;
  if(wp<5){
    int r=wp;
    float v0=src[r*128+lane],v1=src[r*128+lane+32],v2=src[r*128+lane+64],v3=src[r*128+lane+96];
    float s=v0+v1+v2+v3;
    #pragma unroll
    for(int o=16;o;o>>=1) s+=__shfl_xor_sync(0xffffffffu,s,o);
    float m=s*0.0078125f;
    float d0=v0-m,d1=v1-m,d2=v2-m,d3=v3-m;
    float q=d0*d0+d1*d1+d2*d2+d3*d3;
    #pragma unroll
    for(int o=16;o;o>>=1) q+=__shfl_xor_sync(0xffffffffu,q,o);
    float rstd=rsqrtf(q*0.0078125f+1e-5f);
    dst[r*128+lane]   =fmaf(d0*rstd,g[lane],bb[lane]);
    dst[r*128+lane+32]=fmaf(d1*rstd,g[lane+32],bb[lane+32]);
    dst[r*128+lane+64]=fmaf(d2*rstd,g[lane+64],bb[lane+64]);
    dst[r*128+lane+96]=fmaf(d3*rstd,g[lane+96],bb[lane+96]);
  }
}

// ---- transformer with fused token aggregation prologue (R15 scalar form) ----
__global__ __launch_bounds__(256) void k_tr(const float* __restrict__ pos_enc,
    const float* __restrict__ bqkv,
    const float* __restrict__ bo, const float* __restrict__ b1, const float* __restrict__ b2,
    const float* __restrict__ ln1g, const float* __restrict__ ln1b,
    const float* __restrict__ ln2g, const float* __restrict__ ln2b,
    float* __restrict__ out){
  __shared__ float h[5*128];
  __shared__ float qkv[5*384];
  __shared__ float att[4*25];
  __shared__ float tmp[5*256];
  __shared__ int asg[62];
  int b=blockIdx.x, tid=threadIdx.x;
  float* hb = out + (size_t)b*5*128;
  int part=tid>>7, pr=tid&127;
  if(tid<62) asg[tid]=g_assign[tid];
  __syncthreads();
  {
    float a0=0,a1=0,a2=0,a3=0,a4=0;
    const float* pf=&g_pf[((size_t)b*62)*128];
    int c0=part?31:0, c1=part?62:31;
    for(int c=c0;c<c1;c++){
      float v=pf[(size_t)c*128+pr];
      int k=asg[c];
      a0+=(k==0)?v:0.0f; a1+=(k==1)?v:0.0f; a2+=(k==2)?v:0.0f;
      a3+=(k==3)?v:0.0f; a4+=(k==4)?v:0.0f;
    }
    tmp[part*640+0*128+pr]=a0; tmp[part*640+1*128+pr]=a1; tmp[part*640+2*128+pr]=a2;
    tmp[part*640+3*128+pr]=a3; tmp[part*640+4*128+pr]=a4;
  }
  __syncthreads();
  {
    const float szs[NCL]={13.0f,13.0f,12.0f,12.0f,12.0f};
    for(int i=tid;i<640;i+=256){
      int k=i>>7;
      h[i]=(tmp[i]+tmp[640+i])/szs[k]+pos_enc[i];
    }
  }
  __syncthreads();
  for(int l=0;l<3;l++){
    {
      const float* W=&g_WqkvT[(size_t)l*128*384];
      #pragma unroll
      for(int pass=0;pass<2;pass++){
        int col = pass? 256+tid : tid;
        if(pass==0 || tid<128){
          float bv=bqkv[l*384+col];
          float a0=bv,a1=bv,a2=bv,a3=bv,a4=bv;
          #pragma unroll 16
          for(int k=0;k<128;k++){
            float w=W[k*384+col];
            a0=fmaf(h[k],w,a0); a1=fmaf(h[128+k],w,a1); a2=fmaf(h[256+k],w,a2);
            a3=fmaf(h[384+k],w,a3); a4=fmaf(h[512+k],w,a4);
          }
          qkv[0*384+col]=a0; qkv[1*384+col]=a1; qkv[2*384+col]=a2;
          qkv[3*384+col]=a3; qkv[4*384+col]=a4;
        }
      }
    }
    __syncthreads();
    if(tid<100){
      int hd=tid/25, r=tid%25, qt=r/5, kt=r%5;
      float s=0;
      const float* qp=&qkv[qt*384+hd*32];
      const float* kp=&qkv[kt*384+128+hd*32];
      #pragma unroll 8
      for(int d=0;d<32;d++) s=fmaf(qp[d],kp[d],s);
      att[hd*25+qt*5+kt]=s*0.17677669529663689f;
    }
    __syncthreads();
    if(tid<20){
      int hd=tid/5, qt=tid%5;
      float* a=&att[hd*25+qt*5];
      float m=a[0]; for(int i=1;i<5;i++) m=fmaxf(m,a[i]);
      float e[5], s=0;
      for(int i=0;i<5;i++){ e[i]=expf(a[i]-m); s+=e[i]; }
      float inv=1.0f/s;
      for(int i=0;i<5;i++) a[i]=e[i]*inv;
    }
    __syncthreads();
    {
      int hd=pr/32, d=pr%32;
      int q0=part?3:0, q1=part?5:3;
      for(int qt=q0;qt<q1;qt++){
        float s=0;
        #pragma unroll
        for(int kt=0;kt<5;kt++) s=fmaf(att[hd*25+qt*5+kt], qkv[kt*384+256+hd*32+d], s);
        tmp[qt*128+pr]=s;
      }
    }
    __syncthreads();
    {
      const float* W=&g_WoT[(size_t)l*128*128];
      float bv=bo[l*128+pr];
      if(part==0){
        float a0=bv,a1=bv,a2=bv;
        #pragma unroll 16
        for(int k=0;k<128;k++){
          float w=W[k*128+pr];
          a0=fmaf(tmp[k],w,a0); a1=fmaf(tmp[128+k],w,a1); a2=fmaf(tmp[256+k],w,a2);
        }
        qkv[pr]=h[pr]+a0; qkv[128+pr]=h[128+pr]+a1; qkv[256+pr]=h[256+pr]+a2;
      }else{
        float a3=bv,a4=bv;
        #pragma unroll 16
        for(int k=0;k<128;k++){
          float w=W[k*128+pr];
          a3=fmaf(tmp[384+k],w,a3); a4=fmaf(tmp[512+k],w,a4);
        }
        qkv[384+pr]=h[384+pr]+a3; qkv[512+pr]=h[512+pr]+a4;
      }
    }
    __syncthreads();
    ln5b(qkv,h,ln1g+l*128,ln1b+l*128,tid);
    __syncthreads();
    {
      const float* W=&g_W1T[(size_t)l*128*256];
      float bv=b1[l*256+tid];
      float a0=bv,a1=bv,a2=bv,a3=bv,a4=bv;
      #pragma unroll 16
      for(int k=0;k<128;k++){
        float w=W[k*256+tid];
        a0=fmaf(h[k],w,a0); a1=fmaf(h[128+k],w,a1); a2=fmaf(h[256+k],w,a2);
        a3=fmaf(h[384+k],w,a3); a4=fmaf(h[512+k],w,a4);
      }
      tmp[0*256+tid]=fmaxf(a0,0.0f); tmp[1*256+tid]=fmaxf(a1,0.0f);
      tmp[2*256+tid]=fmaxf(a2,0.0f); tmp[3*256+tid]=fmaxf(a3,0.0f);
      tmp[4*256+tid]=fmaxf(a4,0.0f);
    }
    __syncthreads();
    {
      const float* W=&g_W2T[(size_t)l*256*128];
      float bv=b2[l*128+pr];
      if(part==0){
        float a0=bv,a1=bv,a2=bv;
        #pragma unroll 16
        for(int k=0;k<256;k++){
          float w=W[k*128+pr];
          a0=fmaf(tmp[k],w,a0); a1=fmaf(tmp[256+k],w,a1); a2=fmaf(tmp[512+k],w,a2);
        }
        qkv[pr]=h[pr]+a0; qkv[128+pr]=h[128+pr]+a1; qkv[256+pr]=h[256+pr]+a2;
      }else{
        float a3=bv,a4=bv;
        #pragma unroll 16
        for(int k=0;k<256;k++){
          float w=W[k*128+pr];
          a3=fmaf(tmp[768+k],w,a3); a4=fmaf(tmp[1024+k],w,a4);
        }
        qkv[384+pr]=h[384+pr]+a3; qkv[512+pr]=h[512+pr]+a4;
      }
    }
    __syncthreads();
    ln5b(qkv,h,ln2g+l*128,ln2b+l*128,tid);
    __syncthreads();
  }
  for(int i=tid;i<640;i+=256) hb[i]=h[i];
}

extern "C" void kernel_launch(void* const* d_in, const int* in_sizes, int n_in,
                              void* d_out, int out_size){
  const float* x        =(const float*)d_in[0];
  const float* pos_emb  =(const float*)d_in[1];
  const float* proj_w   =(const float*)d_in[2];
  const float* proj_b   =(const float*)d_in[3];
  const float* proj_ln_g=(const float*)d_in[4];
  const float* proj_ln_b=(const float*)d_in[5];
  const float* pos_enc  =(const float*)d_in[6];
  const float* Wqkv     =(const float*)d_in[7];
  const float* bqkv     =(const float*)d_in[8];
  const float* Wo       =(const float*)d_in[9];
  const float* bo       =(const float*)d_in[10];
  const float* W1       =(const float*)d_in[11];
  const float* b1       =(const float*)d_in[12];
  const float* W2       =(const float*)d_in[13];
  const float* b2       =(const float*)d_in[14];
  const float* ln1_g    =(const float*)d_in[15];
  const float* ln1_b    =(const float*)d_in[16];
  const float* ln2_g    =(const float*)d_in[17];
  const float* ln2_b    =(const float*)d_in[18];
  float* out=(float*)d_out;
  k_init<<<192,256>>>(proj_w,Wqkv,Wo,W1,W2);
  k_feat<<<BB*CC,256>>>(x);
  k_projfps<<<128+BB*CC/32+1,256>>>(proj_b,proj_ln_g,proj_ln_b,pos_emb);
  k_tr<<<BB,256>>>(pos_enc,bqkv,bo,b1,b2,ln1_g,ln1_b,ln2_g,ln2_b,out);
}